// round 1
// baseline (speedup 1.0000x reference)
#include <cuda_runtime.h>
#include <cuda_bf16.h>
#include <cstdint>

// ---------------- problem constants ----------------
#define N_NODES 100000
#define W_INF   256
#define W_OUTF  64
#define CCH     2
#define TTYPE   4
#define EDGES   800000
#define MTGT    20000
#define NCLS    4
#define BETA    0.5f

// ---------------- scratch (device globals: allocation-free) ----------------
__device__ float g_X  [N_NODES * 128];   // X_ both channels: [n][c*64+o]
__device__ float g_Acc[N_NODES * 128];   // BETA*X_ + (1-BETA)*scatter
__device__ float g_H2 [N_NODES * 64];    // after linear1+relu
__device__ float g_y  [MTGT * 4];        // fallback y scratch
__device__ float g_loss;
__device__ float g_sc [8];               // (1-BETA)*softmax(conv_weight)[c][t]

// ---------------- packed f32x2 helpers ----------------
#define FMA2(d,a,b,c) asm("fma.rn.f32x2 %0, %1, %2, %3;" : "=l"(d) : "l"(a), "l"(b), "l"(c))
#define PACK2(d,lo,hi) asm("mov.b64 %0, {%1, %2};" : "=l"(d) : "f"(lo), "f"(hi))
#define UNPK2(lo,hi,s) asm("mov.b64 {%0, %1}, %2;" : "=f"(lo), "=f"(hi) : "l"(s))

// ---------------- kernel 0: softmax scales + zero loss ----------------
__global__ void k_prep(const float* __restrict__ cw) {
    if (threadIdx.x == 0) {
        for (int c = 0; c < CCH; c++) {
            float m = -1e30f;
            for (int t = 0; t < TTYPE; t++) m = fmaxf(m, cw[c*TTYPE + t]);
            float e[TTYPE], s = 0.f;
            for (int t = 0; t < TTYPE; t++) { e[t] = expf(cw[c*TTYPE + t] - m); s += e[t]; }
            float inv = (1.0f - BETA) / s;
            for (int t = 0; t < TTYPE; t++) g_sc[c*TTYPE + t] = e[t] * inv;
        }
        g_loss = 0.f;
    }
}

// ---------------- kernel 1: X_ = X @ Wcat ; Acc = BETA*X_ ----------------
// block = 256 thr (8 warps); each warp = 8 rows; block covers 64 rows.
// smem: W [256][128] = 128KB, Xs [8 warps][8 rows][256] = 64KB  -> 192KB dynamic
__global__ void __launch_bounds__(256, 1) k_gemm(const float* __restrict__ X,
                                                 const float* __restrict__ Ws) {
    extern __shared__ float smem[];
    float* Wsh = smem;            // 32768 floats
    float* Xs  = smem + 32768;    // 16384 floats

    const int tid = threadIdx.x, lane = tid & 31, wid = tid >> 5;

    // load W concat: Wsh[k][c*64+o] = Ws[(c*256+k)*64+o]
    for (int i4 = tid; i4 < 8192; i4 += 256) {
        int k  = i4 >> 5;
        int j4 = (i4 & 31) * 4;
        int c  = j4 >> 6, o = j4 & 63;
        *(float4*)&Wsh[k*128 + j4] = *(const float4*)&Ws[(c*256 + k)*64 + o];
    }

    const int row0 = blockIdx.x * 64 + wid * 8;
    #pragma unroll
    for (int r = 0; r < 8; r++) {
        int row = row0 + r;
        if (row < N_NODES) {
            #pragma unroll
            for (int q = lane; q < 64; q += 32)
                *(float4*)&Xs[(wid*8 + r)*256 + q*4] = *(const float4*)&X[(size_t)row*256 + q*4];
        }
    }
    __syncthreads();

    unsigned long long acc[8][2];
    #pragma unroll
    for (int r = 0; r < 8; r++) { acc[r][0] = 0ull; acc[r][1] = 0ull; }

    for (int k4 = 0; k4 < 256; k4 += 4) {
        float4 xv[8];
        #pragma unroll
        for (int r = 0; r < 8; r++) xv[r] = *(float4*)&Xs[(wid*8 + r)*256 + k4];
        #pragma unroll
        for (int kk = 0; kk < 4; kk++) {
            ulonglong2 w2 = *(ulonglong2*)&Wsh[(k4 + kk)*128 + lane*4];
            #pragma unroll
            for (int r = 0; r < 8; r++) {
                float x = (kk == 0) ? xv[r].x : (kk == 1) ? xv[r].y : (kk == 2) ? xv[r].z : xv[r].w;
                unsigned long long xx;
                PACK2(xx, x, x);
                FMA2(acc[r][0], xx, w2.x, acc[r][0]);
                FMA2(acc[r][1], xx, w2.y, acc[r][1]);
            }
        }
    }

    #pragma unroll
    for (int r = 0; r < 8; r++) {
        int row = row0 + r;
        if (row >= N_NODES) continue;
        float4 v;
        UNPK2(v.x, v.y, acc[r][0]);
        UNPK2(v.z, v.w, acc[r][1]);
        *(float4*)&g_X[(size_t)row*128 + lane*4] = v;
        float4 a = make_float4(BETA*v.x, BETA*v.y, BETA*v.z, BETA*v.w);
        *(float4*)&g_Acc[(size_t)row*128 + lane*4] = a;
    }
}

// ---------------- kernel 2: fused 2-channel scatter-add ----------------
// one warp per edge; lanes 0-15 -> channel 0 (cols 0..63), 16-31 -> channel 1.
__global__ void k_scatter(const int* __restrict__ ei, const float* __restrict__ ev) {
    const int t = blockIdx.y;
    const int e = blockIdx.x * 8 + (threadIdx.x >> 5);
    if (e >= EDGES) return;
    const int lane = threadIdx.x & 31;

    const int   row = __ldg(&ei[(t*2 + 0)*EDGES + e]);
    const int   col = __ldg(&ei[(t*2 + 1)*EDGES + e]);
    const float val = __ldg(&ev[t*EDGES + e]);
    const float w   = val * g_sc[(lane >> 4)*TTYPE + t];

    float4 x = *(const float4*)&g_X[(size_t)col*128 + lane*4];
    float* dst = &g_Acc[(size_t)row*128 + lane*4];
    asm volatile("red.global.add.v4.f32 [%0], {%1, %2, %3, %4};"
                 :: "l"(dst), "f"(x.x*w), "f"(x.y*w), "f"(x.z*w), "f"(x.w*w)
                 : "memory");
}

// ---------------- kernel 3: H2 = relu(relu(Acc) @ W1^T + b1) ----------------
// block 256 thr = 8 warps, each warp 2 rows -> 16 rows/block
__global__ void k_lin1(const float* __restrict__ W1, const float* __restrict__ b1) {
    __shared__ float W1t[128 * 66];      // transposed + pad
    __shared__ float Hs[8][2][128];

    const int tid = threadIdx.x, lane = tid & 31, wid = tid >> 5;

    for (int idx = tid; idx < 8192; idx += 256) {
        int o = idx >> 7, j = idx & 127;
        W1t[j*66 + o] = W1[idx];
    }
    __syncthreads();

    const int row0 = blockIdx.x * 16 + wid * 2;
    #pragma unroll
    for (int r = 0; r < 2; r++) {
        int row = row0 + r;
        float4 v = make_float4(0.f, 0.f, 0.f, 0.f);
        if (row < N_NODES) v = *(float4*)&g_Acc[(size_t)row*128 + lane*4];
        float4 h = make_float4(fmaxf(v.x, 0.f), fmaxf(v.y, 0.f), fmaxf(v.z, 0.f), fmaxf(v.w, 0.f));
        *(float4*)&Hs[wid][r][lane*4] = h;
    }
    __syncwarp();

    float a00 = 0.f, a01 = 0.f, a10 = 0.f, a11 = 0.f;
    #pragma unroll 8
    for (int j = 0; j < 128; j++) {
        float h0 = Hs[wid][0][j];
        float h1 = Hs[wid][1][j];
        float w0 = W1t[j*66 + lane];
        float w1 = W1t[j*66 + lane + 32];
        a00 = fmaf(h0, w0, a00);
        a01 = fmaf(h0, w1, a01);
        a10 = fmaf(h1, w0, a10);
        a11 = fmaf(h1, w1, a11);
    }
    const float bb0 = __ldg(&b1[lane]);
    const float bb1 = __ldg(&b1[lane + 32]);
    if (row0 < N_NODES) {
        g_H2[(size_t)row0*64 + lane]      = fmaxf(a00 + bb0, 0.f);
        g_H2[(size_t)row0*64 + lane + 32] = fmaxf(a01 + bb1, 0.f);
    }
    if (row0 + 1 < N_NODES) {
        g_H2[(size_t)(row0+1)*64 + lane]      = fmaxf(a10 + bb0, 0.f);
        g_H2[(size_t)(row0+1)*64 + lane + 32] = fmaxf(a11 + bb1, 0.f);
    }
}

// ---------------- kernel 4: y + loss terms ----------------
__global__ void k_head(const float* __restrict__ lw, const float* __restrict__ lb,
                       const int* __restrict__ tx, const int* __restrict__ tg,
                       float* __restrict__ yout) {
    __shared__ float Wls[4*64 + 4];
    __shared__ float red[256];
    const int tid = threadIdx.x;
    for (int i = tid; i < 260; i += 256) Wls[i] = (i < 256) ? lw[i] : lb[i - 256];
    __syncthreads();

    const int i = blockIdx.x * 256 + tid;
    float lsum = 0.f;
    if (i < MTGT) {
        const int node = __ldg(&tx[i]);
        float l0 = Wls[256], l1 = Wls[257], l2 = Wls[258], l3 = Wls[259];
        const float* h = &g_H2[(size_t)node*64];
        #pragma unroll
        for (int k = 0; k < 64; k += 4) {
            float4 hv = *(const float4*)&h[k];
            l0 += hv.x*Wls[0*64+k] + hv.y*Wls[0*64+k+1] + hv.z*Wls[0*64+k+2] + hv.w*Wls[0*64+k+3];
            l1 += hv.x*Wls[1*64+k] + hv.y*Wls[1*64+k+1] + hv.z*Wls[1*64+k+2] + hv.w*Wls[1*64+k+3];
            l2 += hv.x*Wls[2*64+k] + hv.y*Wls[2*64+k+1] + hv.z*Wls[2*64+k+2] + hv.w*Wls[2*64+k+3];
            l3 += hv.x*Wls[3*64+k] + hv.y*Wls[3*64+k+1] + hv.z*Wls[3*64+k+2] + hv.w*Wls[3*64+k+3];
        }
        yout[i*4+0] = l0; yout[i*4+1] = l1; yout[i*4+2] = l2; yout[i*4+3] = l3;
        float m  = fmaxf(fmaxf(l0, l1), fmaxf(l2, l3));
        float se = expf(l0-m) + expf(l1-m) + expf(l2-m) + expf(l3-m);
        float lse = m + logf(se);
        int t = __ldg(&tg[i]);
        float lt = (t == 0) ? l0 : (t == 1) ? l1 : (t == 2) ? l2 : l3;
        lsum = lse - lt;            // = -log p(target)
    }
    red[tid] = lsum;
    __syncthreads();
    #pragma unroll
    for (int s = 128; s > 0; s >>= 1) {
        if (tid < s) red[tid] += red[tid + s];
        __syncthreads();
    }
    if (tid == 0) atomicAdd(&g_loss, red[0]);
}

// ---------------- kernel 5: finalize loss ----------------
__global__ void k_fin(float* __restrict__ out, int write_loss) {
    if (write_loss) out[0] = g_loss / (float)MTGT;
}

// ---------------- launch ----------------
extern "C" void kernel_launch(void* const* d_in, const int* in_sizes, int n_in,
                              void* d_out, int out_size) {
    const float* X  = (const float*)d_in[0];
    const float* ev = (const float*)d_in[1];
    const float* Ws = (const float*)d_in[2];
    const float* cw = (const float*)d_in[3];
    const float* W1 = (const float*)d_in[4];
    const float* b1 = (const float*)d_in[5];
    const float* lw = (const float*)d_in[6];
    const float* lb = (const float*)d_in[7];
    const int*   ei = (const int*)d_in[8];
    const int*   tx = (const int*)d_in[9];
    const int*   tg = (const int*)d_in[10];
    float* out = (float*)d_out;

    float* yscratch = nullptr;
    cudaGetSymbolAddress((void**)&yscratch, g_y);

    float* yout;
    int write_loss;
    if (out_size == MTGT*4 + 1)      { yout = out + 1;  write_loss = 1; }
    else if (out_size == MTGT*4)     { yout = out;      write_loss = 0; }
    else                             { yout = yscratch; write_loss = 1; }

    k_prep<<<1, 1>>>(cw);

    const size_t gemm_smem = (32768 + 16384) * sizeof(float);  // 192KB
    cudaFuncSetAttribute(k_gemm, cudaFuncAttributeMaxDynamicSharedMemorySize, (int)gemm_smem);
    k_gemm<<<(N_NODES + 63) / 64, 256, gemm_smem>>>(X, Ws);

    dim3 sg((EDGES + 7) / 8, TTYPE);
    k_scatter<<<sg, 256>>>(ei, ev);

    k_lin1<<<(N_NODES + 15) / 16, 256>>>(W1, b1);

    k_head<<<(MTGT + 255) / 256, 256>>>(lw, lb, tx, tg, yout);

    k_fin<<<1, 1>>>(out, write_loss);
}

// round 2
// speedup vs baseline: 1.5298x; 1.5298x over previous
#include <cuda_runtime.h>
#include <cuda_bf16.h>
#include <cstdint>

// ---------------- problem constants ----------------
#define N_NODES 100000
#define W_INF   256
#define W_OUTF  64
#define CCH     2
#define TTYPE   4
#define EDGES   800000
#define TE      (TTYPE*EDGES)          // 3,200,000
#define MTGT    20000
#define NCLS    4
#define BETA    0.5f
#define NB_SCAN 98                     // ceil(100000/1024)

// ---------------- scratch (device globals: allocation-free) ----------------
__device__ float g_X  [N_NODES * 128];   // X_ both channels: [n][c*64+o]
__device__ float g_Acc[N_NODES * 128];   // relu(BETA*X_ + (1-BETA)*scatter)
__device__ float g_H2 [N_NODES * 64];    // after linear1+relu
__device__ float g_y  [MTGT * 4];        // fallback y scratch
__device__ float g_loss;
__device__ float g_sc [8];               // (1-BETA)*softmax(conv_weight)[c][t]

// CSR build scratch
__device__ int   g_cnt [N_NODES];
__device__ int   g_offp[N_NODES];
__device__ int   g_bsum[128];
__device__ int   g_bsumx[128];
__device__ int   g_off [N_NODES + 1];
__device__ int   g_cur [N_NODES];
__device__ int   g_ecol[TE];
__device__ unsigned long long g_epk[TE]; // packed (v0, v1) floats

// ---------------- packed f32x2 helpers ----------------
#define FMA2(d,a,b,c) asm("fma.rn.f32x2 %0, %1, %2, %3;" : "=l"(d) : "l"(a), "l"(b), "l"(c))
#define PACK2(d,lo,hi) asm("mov.b64 %0, {%1, %2};" : "=l"(d) : "f"(lo), "f"(hi))
#define UNPK2(lo,hi,s) asm("mov.b64 {%0, %1}, %2;" : "=f"(lo), "=f"(hi) : "l"(s))

// ---------------- kernel: softmax scales + zero loss ----------------
__global__ void k_prep(const float* __restrict__ cw) {
    if (threadIdx.x == 0) {
        for (int c = 0; c < CCH; c++) {
            float m = -1e30f;
            for (int t = 0; t < TTYPE; t++) m = fmaxf(m, cw[c*TTYPE + t]);
            float e[TTYPE], s = 0.f;
            for (int t = 0; t < TTYPE; t++) { e[t] = expf(cw[c*TTYPE + t] - m); s += e[t]; }
            float inv = (1.0f - BETA) / s;
            for (int t = 0; t < TTYPE; t++) g_sc[c*TTYPE + t] = e[t] * inv;
        }
        g_loss = 0.f;
    }
}

// ---------------- zero the histogram ----------------
__global__ void k_zero() {
    int i = blockIdx.x * 256 + threadIdx.x;
    if (i < N_NODES) g_cnt[i] = 0;
}

// ---------------- GEMM: X_ = X @ Wcat ----------------
__global__ void __launch_bounds__(256, 1) k_gemm(const float* __restrict__ X,
                                                 const float* __restrict__ Ws) {
    extern __shared__ float smem[];
    float* Wsh = smem;            // 32768 floats (128KB)
    float* Xs  = smem + 32768;    // 16384 floats (64KB)

    const int tid = threadIdx.x, lane = tid & 31, wid = tid >> 5;

    for (int i4 = tid; i4 < 8192; i4 += 256) {
        int k  = i4 >> 5;
        int j4 = (i4 & 31) * 4;
        int c  = j4 >> 6, o = j4 & 63;
        *(float4*)&Wsh[k*128 + j4] = *(const float4*)&Ws[(c*256 + k)*64 + o];
    }

    const int row0 = blockIdx.x * 64 + wid * 8;
    #pragma unroll
    for (int r = 0; r < 8; r++) {
        int row = row0 + r;
        if (row < N_NODES) {
            #pragma unroll
            for (int q = lane; q < 64; q += 32)
                *(float4*)&Xs[(wid*8 + r)*256 + q*4] = *(const float4*)&X[(size_t)row*256 + q*4];
        }
    }
    __syncthreads();

    unsigned long long acc[8][2];
    #pragma unroll
    for (int r = 0; r < 8; r++) { acc[r][0] = 0ull; acc[r][1] = 0ull; }

    for (int k4 = 0; k4 < 256; k4 += 4) {
        float4 xv[8];
        #pragma unroll
        for (int r = 0; r < 8; r++) xv[r] = *(float4*)&Xs[(wid*8 + r)*256 + k4];
        #pragma unroll
        for (int kk = 0; kk < 4; kk++) {
            ulonglong2 w2 = *(ulonglong2*)&Wsh[(k4 + kk)*128 + lane*4];
            #pragma unroll
            for (int r = 0; r < 8; r++) {
                float x = (kk == 0) ? xv[r].x : (kk == 1) ? xv[r].y : (kk == 2) ? xv[r].z : xv[r].w;
                unsigned long long xx;
                PACK2(xx, x, x);
                FMA2(acc[r][0], xx, w2.x, acc[r][0]);
                FMA2(acc[r][1], xx, w2.y, acc[r][1]);
            }
        }
    }

    #pragma unroll
    for (int r = 0; r < 8; r++) {
        int row = row0 + r;
        if (row >= N_NODES) continue;
        float4 v;
        UNPK2(v.x, v.y, acc[r][0]);
        UNPK2(v.z, v.w, acc[r][1]);
        *(float4*)&g_X[(size_t)row*128 + lane*4] = v;
    }
}

// ---------------- histogram of destination rows ----------------
__global__ void k_hist(const int* __restrict__ ei) {
    const int t = blockIdx.y;
    const int e = blockIdx.x * 256 + threadIdx.x;
    if (e >= EDGES) return;
    int row = __ldg(&ei[(t*2 + 0)*EDGES + e]);
    atomicAdd(&g_cnt[row], 1);
}

// ---------------- scan stage 1: per-block (1024 elems) ----------------
__global__ void k_scan1() {
    __shared__ int s[256];
    const int tid = threadIdx.x;
    const int base = blockIdx.x * 1024 + tid * 4;
    int v0 = 0, v1 = 0, v2 = 0, v3 = 0;
    if (base + 3 < N_NODES) {
        int4 q = *(const int4*)&g_cnt[base];
        v0 = q.x; v1 = q.y; v2 = q.z; v3 = q.w;
    } else {
        if (base     < N_NODES) v0 = g_cnt[base];
        if (base + 1 < N_NODES) v1 = g_cnt[base + 1];
        if (base + 2 < N_NODES) v2 = g_cnt[base + 2];
        if (base + 3 < N_NODES) v3 = g_cnt[base + 3];
    }
    int tsum = v0 + v1 + v2 + v3;
    s[tid] = tsum;
    __syncthreads();
    for (int d = 1; d < 256; d <<= 1) {
        int t = 0;
        if (tid >= d) t = s[tid - d];
        __syncthreads();
        if (tid >= d) s[tid] += t;
        __syncthreads();
    }
    int excl = s[tid] - tsum;
    if (base     < N_NODES) g_offp[base]     = excl;           excl += v0;
    if (base + 1 < N_NODES) g_offp[base + 1] = excl;           excl += v1;
    if (base + 2 < N_NODES) g_offp[base + 2] = excl;           excl += v2;
    if (base + 3 < N_NODES) g_offp[base + 3] = excl;
    if (tid == 255) g_bsum[blockIdx.x] = s[255];
}

// ---------------- scan stage 2: block sums ----------------
__global__ void k_scan2() {
    __shared__ int s[128];
    const int tid = threadIdx.x;
    int v = (tid < NB_SCAN) ? g_bsum[tid] : 0;
    s[tid] = v;
    __syncthreads();
    for (int d = 1; d < 128; d <<= 1) {
        int t = 0;
        if (tid >= d) t = s[tid - d];
        __syncthreads();
        if (tid >= d) s[tid] += t;
        __syncthreads();
    }
    g_bsumx[tid] = s[tid] - v;
}

// ---------------- scan stage 3: finalize offsets + cursors ----------------
__global__ void k_scan3() {
    int i = blockIdx.x * 256 + threadIdx.x;
    if (i < N_NODES) {
        int o = g_offp[i] + g_bsumx[i >> 10];
        g_off[i] = o;
        g_cur[i] = o;
    }
    if (i == 0) g_off[N_NODES] = TE;
}

// ---------------- bucket: place edges into CSR slots ----------------
__global__ void k_bucket(const int* __restrict__ ei, const float* __restrict__ ev) {
    const int t = blockIdx.y;
    const int e = blockIdx.x * 256 + threadIdx.x;
    if (e >= EDGES) return;
    int   row = __ldg(&ei[(t*2 + 0)*EDGES + e]);
    int   col = __ldg(&ei[(t*2 + 1)*EDGES + e]);
    float val = __ldg(&ev[t*EDGES + e]);
    int pos = atomicAdd(&g_cur[row], 1);
    float v0 = val * g_sc[t];
    float v1 = val * g_sc[4 + t];
    g_ecol[pos] = col;
    g_epk[pos] = ((unsigned long long)__float_as_uint(v1) << 32) | __float_as_uint(v0);
}

// ---------------- gather: Acc[n] = relu(BETA*X_[n] + sum msgs) ----------------
__global__ void __launch_bounds__(256) k_gather() {
    const int lane = threadIdx.x & 31;
    const int n = blockIdx.x * 8 + (threadIdx.x >> 5);
    if (n >= N_NODES) return;

    const int s0 = __ldg(&g_off[n]);
    const int s1 = __ldg(&g_off[n + 1]);

    float4 x = *(const float4*)&g_X[(size_t)n*128 + lane*4];
    float4 acc = make_float4(BETA*x.x, BETA*x.y, BETA*x.z, BETA*x.w);

    const unsigned mask = 0xffffffffu;
    for (int base = s0; base < s1; base += 32) {
        int m = s1 - base; if (m > 32) m = 32;
        int col = 0; unsigned long long pv = 0;
        if (lane < m) {
            col = __ldg(&g_ecol[base + lane]);
            pv  = __ldg(&g_epk[base + lane]);
        }
        int j = 0;
        for (; j + 1 < m; j += 2) {
            int c0 = __shfl_sync(mask, col, j);
            int c1 = __shfl_sync(mask, col, j + 1);
            unsigned long long p0 = __shfl_sync(mask, pv, j);
            unsigned long long p1 = __shfl_sync(mask, pv, j + 1);
            float4 x0 = *(const float4*)&g_X[(size_t)c0*128 + lane*4];
            float4 x1 = *(const float4*)&g_X[(size_t)c1*128 + lane*4];
            float w0 = (lane < 16) ? __uint_as_float((unsigned)p0) : __uint_as_float((unsigned)(p0 >> 32));
            float w1 = (lane < 16) ? __uint_as_float((unsigned)p1) : __uint_as_float((unsigned)(p1 >> 32));
            acc.x = fmaf(x0.x, w0, acc.x); acc.y = fmaf(x0.y, w0, acc.y);
            acc.z = fmaf(x0.z, w0, acc.z); acc.w = fmaf(x0.w, w0, acc.w);
            acc.x = fmaf(x1.x, w1, acc.x); acc.y = fmaf(x1.y, w1, acc.y);
            acc.z = fmaf(x1.z, w1, acc.z); acc.w = fmaf(x1.w, w1, acc.w);
        }
        if (j < m) {
            int c0 = __shfl_sync(mask, col, j);
            unsigned long long p0 = __shfl_sync(mask, pv, j);
            float4 x0 = *(const float4*)&g_X[(size_t)c0*128 + lane*4];
            float w0 = (lane < 16) ? __uint_as_float((unsigned)p0) : __uint_as_float((unsigned)(p0 >> 32));
            acc.x = fmaf(x0.x, w0, acc.x); acc.y = fmaf(x0.y, w0, acc.y);
            acc.z = fmaf(x0.z, w0, acc.z); acc.w = fmaf(x0.w, w0, acc.w);
        }
    }
    float4 out = make_float4(fmaxf(acc.x, 0.f), fmaxf(acc.y, 0.f),
                             fmaxf(acc.z, 0.f), fmaxf(acc.w, 0.f));
    *(float4*)&g_Acc[(size_t)n*128 + lane*4] = out;
}

// ---------------- lin1: H2 = relu(Acc @ W1^T + b1), 8 rows/warp ----------------
// dyn smem: W1q float4[64*32] (32KB, XOR-swizzled) + Hs float[8][8*128] (32KB)
__global__ void __launch_bounds__(256) k_lin1(const float* __restrict__ W1,
                                              const float* __restrict__ b1) {
    extern __shared__ float sm[];
    float4* W1q = (float4*)sm;          // 2048 float4
    float*  Hsb = sm + 8192;            // 8192 floats

    const int tid = threadIdx.x, lane = tid & 31, wid = tid >> 5;

    // W1q[jp*32 + (o ^ (jp&31))] = (W1[o][2jp], W1[o][2jp+1], W1[o+32][2jp], W1[o+32][2jp+1])
    for (int idx2 = tid; idx2 < 4096; idx2 += 256) {
        int jp = idx2 & 63, o = idx2 >> 6;
        float2 w = *(const float2*)&W1[o*128 + jp*2];
        int slot = jp*32 + ((o & 31) ^ (jp & 31));
        ((float2*)&W1q[slot])[o >> 5] = w;
    }

    float* HsW = Hsb + wid * 1024;   // [r][j] for this warp's 8 rows
    const int row0 = blockIdx.x * 64 + wid * 8;
    #pragma unroll
    for (int r = 0; r < 8; r++) {
        int row = row0 + r;
        float4 v = make_float4(0.f, 0.f, 0.f, 0.f);
        if (row < N_NODES) v = *(const float4*)&g_Acc[(size_t)row*128 + lane*4];
        *(float4*)&HsW[r*128 + lane*4] = v;   // already relu'd by k_gather
    }
    __syncthreads();

    float acc0[8], acc1[8];
    #pragma unroll
    for (int r = 0; r < 8; r++) { acc0[r] = 0.f; acc1[r] = 0.f; }

    #pragma unroll 4
    for (int j2 = 0; j2 < 64; j2++) {
        float4 q = W1q[j2*32 + (lane ^ (j2 & 31))];
        #pragma unroll
        for (int r = 0; r < 8; r++) {
            float2 h = *(const float2*)&HsW[r*128 + j2*2];
            acc0[r] = fmaf(h.y, q.y, fmaf(h.x, q.x, acc0[r]));
            acc1[r] = fmaf(h.y, q.w, fmaf(h.x, q.z, acc1[r]));
        }
    }

    const float bb0 = __ldg(&b1[lane]);
    const float bb1 = __ldg(&b1[lane + 32]);
    #pragma unroll
    for (int r = 0; r < 8; r++) {
        int row = row0 + r;
        if (row < N_NODES) {
            g_H2[(size_t)row*64 + lane]      = fmaxf(acc0[r] + bb0, 0.f);
            g_H2[(size_t)row*64 + lane + 32] = fmaxf(acc1[r] + bb1, 0.f);
        }
    }
}

// ---------------- head: y + loss terms ----------------
__global__ void k_head(const float* __restrict__ lw, const float* __restrict__ lb,
                       const int* __restrict__ tx, const int* __restrict__ tg,
                       float* __restrict__ yout) {
    __shared__ float Wls[4*64 + 4];
    __shared__ float red[256];
    const int tid = threadIdx.x;
    for (int i = tid; i < 260; i += 256) Wls[i] = (i < 256) ? lw[i] : lb[i - 256];
    __syncthreads();

    const int i = blockIdx.x * 256 + tid;
    float lsum = 0.f;
    if (i < MTGT) {
        const int node = __ldg(&tx[i]);
        float l0 = Wls[256], l1 = Wls[257], l2 = Wls[258], l3 = Wls[259];
        const float* h = &g_H2[(size_t)node*64];
        #pragma unroll
        for (int k = 0; k < 64; k += 4) {
            float4 hv = *(const float4*)&h[k];
            l0 += hv.x*Wls[0*64+k] + hv.y*Wls[0*64+k+1] + hv.z*Wls[0*64+k+2] + hv.w*Wls[0*64+k+3];
            l1 += hv.x*Wls[1*64+k] + hv.y*Wls[1*64+k+1] + hv.z*Wls[1*64+k+2] + hv.w*Wls[1*64+k+3];
            l2 += hv.x*Wls[2*64+k] + hv.y*Wls[2*64+k+1] + hv.z*Wls[2*64+k+2] + hv.w*Wls[2*64+k+3];
            l3 += hv.x*Wls[3*64+k] + hv.y*Wls[3*64+k+1] + hv.z*Wls[3*64+k+2] + hv.w*Wls[3*64+k+3];
        }
        yout[i*4+0] = l0; yout[i*4+1] = l1; yout[i*4+2] = l2; yout[i*4+3] = l3;
        float m  = fmaxf(fmaxf(l0, l1), fmaxf(l2, l3));
        float se = expf(l0-m) + expf(l1-m) + expf(l2-m) + expf(l3-m);
        float lse = m + logf(se);
        int t = __ldg(&tg[i]);
        float lt = (t == 0) ? l0 : (t == 1) ? l1 : (t == 2) ? l2 : l3;
        lsum = lse - lt;
    }
    red[tid] = lsum;
    __syncthreads();
    #pragma unroll
    for (int s = 128; s > 0; s >>= 1) {
        if (tid < s) red[tid] += red[tid + s];
        __syncthreads();
    }
    if (tid == 0) atomicAdd(&g_loss, red[0]);
}

__global__ void k_fin(float* __restrict__ out, int write_loss) {
    if (write_loss) out[0] = g_loss / (float)MTGT;
}

// ---------------- launch ----------------
extern "C" void kernel_launch(void* const* d_in, const int* in_sizes, int n_in,
                              void* d_out, int out_size) {
    const float* X  = (const float*)d_in[0];
    const float* ev = (const float*)d_in[1];
    const float* Ws = (const float*)d_in[2];
    const float* cw = (const float*)d_in[3];
    const float* W1 = (const float*)d_in[4];
    const float* b1 = (const float*)d_in[5];
    const float* lw = (const float*)d_in[6];
    const float* lb = (const float*)d_in[7];
    const int*   ei = (const int*)d_in[8];
    const int*   tx = (const int*)d_in[9];
    const int*   tg = (const int*)d_in[10];
    float* out = (float*)d_out;

    float* yscratch = nullptr;
    cudaGetSymbolAddress((void**)&yscratch, g_y);

    float* yout;
    int write_loss;
    if (out_size == MTGT*4 + 1)      { yout = out + 1;  write_loss = 1; }
    else if (out_size == MTGT*4)     { yout = out;      write_loss = 0; }
    else                             { yout = yscratch; write_loss = 1; }

    k_prep<<<1, 32>>>(cw);
    k_zero<<<(N_NODES + 255)/256, 256>>>();

    const size_t gemm_smem = (32768 + 16384) * sizeof(float);  // 192KB
    cudaFuncSetAttribute(k_gemm, cudaFuncAttributeMaxDynamicSharedMemorySize, (int)gemm_smem);
    k_gemm<<<(N_NODES + 63) / 64, 256, gemm_smem>>>(X, Ws);

    dim3 eg((EDGES + 255)/256, TTYPE);
    k_hist<<<eg, 256>>>(ei);
    k_scan1<<<NB_SCAN, 256>>>();
    k_scan2<<<1, 128>>>();
    k_scan3<<<(N_NODES + 255)/256, 256>>>();
    k_bucket<<<eg, 256>>>(ei, ev);
    k_gather<<<(N_NODES + 7)/8, 256>>>();

    const size_t lin1_smem = 65536;
    cudaFuncSetAttribute(k_lin1, cudaFuncAttributeMaxDynamicSharedMemorySize, (int)lin1_smem);
    k_lin1<<<(N_NODES + 63)/64, 256, lin1_smem>>>(W1, b1);

    k_head<<<(MTGT + 255)/256, 256>>>(lw, lb, tx, tg, yout);
    k_fin<<<1, 1>>>(out, write_loss);
}